// round 3
// baseline (speedup 1.0000x reference)
#include <cuda_runtime.h>
#include <cuda_fp16.h>

#define T_STEPS 1024
#define BATCH   64
#define ICH     512
#define HCH     512
#define G4      2048
#define NLAYER  2
#define NBLK    128

// ---------------- scratch (static device globals; no allocation) ------------
__device__ __align__(16) float  g_xi[134217728];   // [T][B][2048] reused per layer
__device__ __align__(16) float  g_hs0[33554432];   // layer0 h sequence [T][B][512]
__device__ __align__(16) __half g_hbuf[2][BATCH*HCH];
__device__ __align__(16) __half g_Wi_r[NLAYER*G4*ICH];
__device__ __align__(16) __half g_Wh_r[NLAYER*G4*HCH];
__device__ __align__(16) float  g_bias_r[NLAYER*G4];
__device__ int g_flag[NBLK];

// ---------------- helpers ---------------------------------------------------
__device__ __forceinline__ void mma_f16(float acc[4],
                                        unsigned a0, unsigned a1, unsigned a2, unsigned a3,
                                        unsigned b0, unsigned b1) {
    asm volatile(
        "mma.sync.aligned.m16n8k16.row.col.f32.f16.f16.f32 "
        "{%0,%1,%2,%3},{%4,%5,%6,%7},{%8,%9},{%0,%1,%2,%3};"
        : "+f"(acc[0]), "+f"(acc[1]), "+f"(acc[2]), "+f"(acc[3])
        : "r"(a0), "r"(a1), "r"(a2), "r"(a3), "r"(b0), "r"(b1));
}

__device__ __forceinline__ float sigmf(float x) { return 1.f / (1.f + __expf(-x)); }

__device__ __forceinline__ int ld_acq(const int* p) {
    int v;
    asm volatile("ld.acquire.gpu.global.b32 %0, [%1];" : "=r"(v) : "l"(p) : "memory");
    return v;
}
__device__ __forceinline__ void st_rel(int* p, int v) {
    asm volatile("st.release.gpu.global.b32 [%0], %1;" :: "l"(p), "r"(v) : "memory");
}

// ---------------- init: reset flags (needed per graph replay) ---------------
__global__ void k_init() { g_flag[threadIdx.x] = 0; }

// ---------------- reorder weights to interleaved-gate fp16 ------------------
// dest row n' = 4*j + s  <->  source row s*512 + j   (s in {f,i,o,g})
__global__ void k_reorder(const float* __restrict__ Wi, const float* __restrict__ bi,
                          const float* __restrict__ Wh, const float* __restrict__ bh) {
    unsigned idx = blockIdx.x * 256u + threadIdx.x;   // over 2*2048*512 = 2097152
    if (idx >= 2097152u) return;
    int k  = idx & 511;
    int np = (idx >> 9) & 2047;
    int l  = idx >> 20;
    int s  = np & 3;
    int j  = np >> 2;
    size_t src = ((size_t)l * G4 + s * 512 + j) * 512 + k;
    g_Wi_r[idx] = __float2half_rn(Wi[src]);
    g_Wh_r[idx] = __float2half_rn(Wh[src]);
    if (k == 0)
        g_bias_r[l * G4 + np] = bi[l * G4 + s * 512 + j] + bh[l * G4 + s * 512 + j];
}

// ---------------- big input-projection GEMM ---------------------------------
// C[65536, 2048] = A[65536, 512] (fp32->fp16) x Wr[2048, 512]^T + bias
__global__ __launch_bounds__(256) void k_gemm(const float* __restrict__ Ain, int layer) {
    __shared__ unsigned As[128][20];
    __shared__ unsigned Bs[64][20];

    const float*  A    = Ain ? Ain : g_hs0;
    const __half* W    = g_Wi_r + (size_t)layer * G4 * ICH;
    const float*  bias = g_bias_r + layer * G4;
    float*        C    = g_xi;

    int n0 = blockIdx.x * 64, m0 = blockIdx.y * 128;
    int tid = threadIdx.x, lane = tid & 31, warp = tid >> 5;
    int q = lane & 3, gr = lane >> 2;
    int wm = warp & 3, wn = warp >> 2;

    float acc[2][4][4];
#pragma unroll
    for (int mi = 0; mi < 2; mi++)
#pragma unroll
        for (int ni = 0; ni < 4; ni++)
#pragma unroll
            for (int e = 0; e < 4; e++) acc[mi][ni][e] = 0.f;

    for (int k0 = 0; k0 < 512; k0 += 32) {
#pragma unroll
        for (int i = 0; i < 4; i++) {
            int f4 = tid + i * 256;
            int r = f4 >> 3, c4 = f4 & 7;
            float4 v = *(const float4*)&A[(size_t)(m0 + r) * 512 + k0 + c4 * 4];
            __half2 h01 = __floats2half2_rn(v.x, v.y);
            __half2 h23 = __floats2half2_rn(v.z, v.w);
            As[r][c4 * 2]     = *(unsigned*)&h01;
            As[r][c4 * 2 + 1] = *(unsigned*)&h23;
        }
#pragma unroll
        for (int i = 0; i < 2; i++) {
            int e = tid + i * 256;
            int r = e >> 3, u = e & 7;
            uint2 v = *(const uint2*)(W + (size_t)(n0 + r) * 512 + k0 + u * 4);
            Bs[r][u * 2] = v.x;
            Bs[r][u * 2 + 1] = v.y;
        }
        __syncthreads();

#pragma unroll
        for (int kt = 0; kt < 2; kt++) {
            unsigned a[2][4];
#pragma unroll
            for (int mi = 0; mi < 2; mi++) {
                int r0 = wm * 32 + mi * 16 + gr;
                a[mi][0] = As[r0][kt * 8 + q];
                a[mi][1] = As[r0 + 8][kt * 8 + q];
                a[mi][2] = As[r0][kt * 8 + q + 4];
                a[mi][3] = As[r0 + 8][kt * 8 + q + 4];
            }
#pragma unroll
            for (int ni = 0; ni < 4; ni++) {
                int br = wn * 32 + ni * 8 + gr;
                unsigned b0 = Bs[br][kt * 8 + q];
                unsigned b1 = Bs[br][kt * 8 + q + 4];
#pragma unroll
                for (int mi = 0; mi < 2; mi++)
                    mma_f16(acc[mi][ni], a[mi][0], a[mi][1], a[mi][2], a[mi][3], b0, b1);
            }
        }
        __syncthreads();
    }

#pragma unroll
    for (int mi = 0; mi < 2; mi++)
#pragma unroll
        for (int ni = 0; ni < 4; ni++) {
            int row  = m0 + wm * 32 + mi * 16 + gr;
            int ncol = n0 + wn * 32 + ni * 8 + 2 * q;
            float2 bb = *(const float2*)&bias[ncol];
            float2 o;
            o.x = acc[mi][ni][0] + bb.x; o.y = acc[mi][ni][1] + bb.y;
            *(float2*)&C[(size_t)row * G4 + ncol] = o;
            o.x = acc[mi][ni][2] + bb.x; o.y = acc[mi][ni][3] + bb.y;
            *(float2*)&C[(size_t)(row + 8) * G4 + ncol] = o;
        }
}

// ---------------- persistent recurrent kernel (dataflow sync) ---------------
// 128 blocks x 128 threads. Block b owns gate' rows [16b,16b+16) <-> h cols [4b,4b+4).
// Producer publishes its h-slice with st.release + per-block flag; consumers
// acquire-poll all 128 flags in parallel (one per thread) + __syncthreads_and.
__global__ __launch_bounds__(128, 1) void k_lstm(int layer,
                                                 const float* __restrict__ h0l,
                                                 const float* __restrict__ c0l,
                                                 float* __restrict__ ybase,
                                                 float* __restrict__ hT,
                                                 float* __restrict__ cT) {
    __shared__ uint2 sWh[16][132];   // [gate' row local][uint2 over K=512 halves]
    __shared__ float sG[64][20];     // gate accumulators [batch][local n']

    int b = blockIdx.x, tid = threadIdx.x;
    int lane = tid & 31, warp = tid >> 5;
    int q = lane & 3, gr = lane >> 2;
    float* hseq = (layer == 0) ? g_hs0 : ybase;

    // load this block's Wh slice (16 x 512 fp16) into smem
    const uint2* WhU = (const uint2*)(g_Wh_r + (size_t)layer * G4 * HCH);
#pragma unroll
    for (int i = 0; i < 16; i++) {
        int w = tid + i * 128;
        int r = w >> 7, c = w & 127;
        sWh[r][c] = WhU[(size_t)(16 * b + r) * 128 + c];
    }

    // init c (registers) and h buffer slice, publish flag=1 (h_0 ready)
    float creg[2];
#pragma unroll
    for (int s = 0; s < 2; s++) {
        int idx = tid + s * 128;
        int batch = idx >> 2, jl = idx & 3, col = 4 * b + jl;
        creg[s] = c0l[batch * HCH + col];
        g_hbuf[0][batch * HCH + col] = __float2half_rn(h0l[batch * HCH + col]);
    }
    __threadfence();
    __syncthreads();
    if (tid == 0) st_rel(&g_flag[b], 1);

    const int rb   = 16 * warp + gr;     // batch row for A fragments
    const int base = rb * 128;
    const int b0i  = tid >> 2,  j0 = tid & 3;
    const int b1i  = (tid + 128) >> 2, j1 = tid & 3;

    for (int t = 0; t < T_STEPS; t++) {
        // prefetch xi_t (DRAM) before the wait so latency hides under sync+mma
        const float* xit = g_xi + (size_t)t * BATCH * G4;
        float4 xv0 = *(const float4*)&xit[b0i * G4 + 16 * b + 4 * j0];
        float4 xv1 = *(const float4*)&xit[b1i * G4 + 16 * b + 4 * j1];

        // wait for all producers to publish step-t h (flag >= t+1)
        {
            int need = t + 1;
            bool ok = (ld_acq(&g_flag[tid]) >= need);
            while (!__syncthreads_and(ok))
                ok = (ld_acq(&g_flag[tid]) >= need);
        }

        const uint2* hb = (const uint2*)g_hbuf[t & 1];
        float acc[2][4];
#pragma unroll
        for (int nt = 0; nt < 2; nt++)
#pragma unroll
            for (int e = 0; e < 4; e++) acc[nt][e] = 0.f;

        // 2-deep software pipeline over 4 batches of 8 kt-iterations.
        // uint2 covers phys k = 4*wi..4*wi+3 for BOTH A and B (same K-perm),
        // so every 32B L2 sector is fully consumed.
        uint2 va[2][8], vb[2][8];
#pragma unroll
        for (int u = 0; u < 8; u++) {
            int wi = 4 * u + q;
            va[0][u] = __ldcg(&hb[base + wi]);
            vb[0][u] = __ldcg(&hb[base + 1024 + wi]);
        }
#pragma unroll
        for (int ko = 0; ko < 4; ko++) {
            int cur = ko & 1;
            if (ko < 3) {
#pragma unroll
                for (int u = 0; u < 8; u++) {
                    int wi = 32 * (ko + 1) + 4 * u + q;
                    va[cur ^ 1][u] = __ldcg(&hb[base + wi]);
                    vb[cur ^ 1][u] = __ldcg(&hb[base + 1024 + wi]);
                }
            }
#pragma unroll
            for (int u = 0; u < 8; u++) {
                int wi = 32 * ko + 4 * u + q;
#pragma unroll
                for (int nt = 0; nt < 2; nt++) {
                    uint2 wv = sWh[nt * 8 + gr][wi];
                    mma_f16(acc[nt], va[cur][u].x, vb[cur][u].x,
                            va[cur][u].y, vb[cur][u].y, wv.x, wv.y);
                }
            }
        }

        // accumulators -> smem (natural [batch][gate'] layout)
#pragma unroll
        for (int nt = 0; nt < 2; nt++) {
            int nc = nt * 8 + 2 * q;
            *(float2*)&sG[16 * warp + gr][nc]     = make_float2(acc[nt][0], acc[nt][1]);
            *(float2*)&sG[16 * warp + gr + 8][nc] = make_float2(acc[nt][2], acc[nt][3]);
        }
        __syncthreads();

        // elementwise LSTM cell update; publish h slice ASAP
        __half* hn = g_hbuf[(t + 1) & 1];
        float hv[2], cv[2];
#pragma unroll
        for (int s = 0; s < 2; s++) {
            int idx = tid + s * 128;
            int batch = idx >> 2, jl = idx & 3, col = 4 * b + jl;
            float4 xv = s ? xv1 : xv0;
            float gf = sG[batch][4 * jl + 0] + xv.x;
            float gi = sG[batch][4 * jl + 1] + xv.y;
            float go = sG[batch][4 * jl + 2] + xv.z;
            float gg = sG[batch][4 * jl + 3] + xv.w;
            float f  = sigmf(gf);
            float ii = sigmf(gi);
            float o  = sigmf(go);
            float g  = tanhf(gg);
            float c  = creg[s] * f + ii * g;
            creg[s]  = c;
            float h  = o * tanhf(c);
            hv[s] = h; cv[s] = c;
            hn[batch * HCH + col] = __float2half_rn(h);
        }
        __threadfence();
        __syncthreads();
        if (tid == 0) st_rel(&g_flag[b], t + 2);

        // off-critical-path: fp32 sequence output (+ finals)
#pragma unroll
        for (int s = 0; s < 2; s++) {
            int idx = tid + s * 128;
            int batch = idx >> 2, jl = idx & 3, col = 4 * b + jl;
            hseq[(size_t)t * BATCH * HCH + batch * HCH + col] = hv[s];
            if (t == T_STEPS - 1) {
                hT[batch * HCH + col] = hv[s];
                cT[batch * HCH + col] = cv[s];
            }
        }
    }
}

// ---------------- launch ----------------------------------------------------
extern "C" void kernel_launch(void* const* d_in, const int* in_sizes, int n_in,
                              void* d_out, int out_size) {
    const float* x  = (const float*)d_in[0];
    const float* Wi = (const float*)d_in[1];
    const float* bi = (const float*)d_in[2];
    const float* Wh = (const float*)d_in[3];
    const float* bh = (const float*)d_in[4];
    const float* h0 = (const float*)d_in[5];
    const float* c0 = (const float*)d_in[6];

    float* out = (float*)d_out;
    float* y   = out;                                   // [T,B,HC]
    float* hsO = out + (size_t)T_STEPS * BATCH * HCH;   // [L,B,HC]
    float* csO = hsO + (size_t)NLAYER * BATCH * HCH;    // [L,B,HC]

    k_reorder<<<8192, 256>>>(Wi, bi, Wh, bh);

    // layer 0
    k_gemm<<<dim3(32, 512), 256>>>(x, 0);
    k_init<<<1, NBLK>>>();
    k_lstm<<<NBLK, 128>>>(0, h0, c0, y, hsO, csO);

    // layer 1
    k_gemm<<<dim3(32, 512), 256>>>(nullptr, 1);
    k_init<<<1, NBLK>>>();
    k_lstm<<<NBLK, 128>>>(1, h0 + BATCH * HCH, c0 + BATCH * HCH, y,
                          hsO + BATCH * HCH, csO + BATCH * HCH);

    (void)in_sizes; (void)n_in; (void)out_size;
}

// round 7
// speedup vs baseline: 2.4282x; 2.4282x over previous
#include <cuda_runtime.h>
#include <cuda_fp16.h>

#define T_STEPS 1024
#define BATCH   64
#define ICH     512
#define HCH     512
#define G4      2048
#define NLAYER  2
#define NBLK    128

// ---------------- scratch (static device globals; no allocation) ------------
__device__ __align__(16) float  g_xi[134217728];   // [T][B][2048] reused per layer
__device__ __align__(16) __half g_hs0[33554432];   // layer0 h sequence [T][B][512] fp16
__device__ __align__(16) __half g_hbuf[2][BATCH*HCH];
__device__ __align__(16) __half g_Wi_r[NLAYER*G4*ICH];
__device__ __align__(16) __half g_Wh_r[NLAYER*G4*HCH];
__device__ __align__(16) float  g_bias_r[NLAYER*G4];
__device__ int g_cnt;

// ---------------- helpers ---------------------------------------------------
__device__ __forceinline__ void mma_f16(float acc[4],
                                        unsigned a0, unsigned a1, unsigned a2, unsigned a3,
                                        unsigned b0, unsigned b1) {
    asm volatile(
        "mma.sync.aligned.m16n8k16.row.col.f32.f16.f16.f32 "
        "{%0,%1,%2,%3},{%4,%5,%6,%7},{%8,%9},{%0,%1,%2,%3};"
        : "+f"(acc[0]), "+f"(acc[1]), "+f"(acc[2]), "+f"(acc[3])
        : "r"(a0), "r"(a1), "r"(a2), "r"(a3), "r"(b0), "r"(b1));
}

__device__ __forceinline__ float sigmf(float x) {
    return __fdividef(1.f, 1.f + __expf(-x));
}
__device__ __forceinline__ float tanhfast(float x) {
    // 1 - 2/(e^{2x}+1); overflow-safe: e->inf => 1, e->0 => -1
    float e = __expf(2.f * x);
    return 1.f - __fdividef(2.f, e + 1.f);
}

__device__ __forceinline__ int ld_relaxed(const int* p) {
    int v;
    asm volatile("ld.relaxed.gpu.global.b32 %0, [%1];" : "=r"(v) : "l"(p) : "memory");
    return v;
}
__device__ __forceinline__ void red_add_relaxed(int* p, int v) {
    asm volatile("red.relaxed.gpu.global.add.s32 [%0], %1;" :: "l"(p), "r"(v) : "memory");
}
__device__ __forceinline__ void fence_gpu() {
    asm volatile("fence.acq_rel.gpu;" ::: "memory");
}

// ---------------- init: reset counter (needed per graph replay) -------------
__global__ void k_init() { g_cnt = 0; }

// ---------------- reorder weights to interleaved-gate fp16 ------------------
// dest row n' = 4*j + s  <->  source row s*512 + j   (s in {f,i,o,g})
__global__ void k_reorder(const float* __restrict__ Wi, const float* __restrict__ bi,
                          const float* __restrict__ Wh, const float* __restrict__ bh) {
    unsigned idx = blockIdx.x * 256u + threadIdx.x;   // over 2*2048*512 = 2097152
    if (idx >= 2097152u) return;
    int k  = idx & 511;
    int np = (idx >> 9) & 2047;
    int l  = idx >> 20;
    int s  = np & 3;
    int j  = np >> 2;
    size_t src = ((size_t)l * G4 + s * 512 + j) * 512 + k;
    g_Wi_r[idx] = __float2half_rn(Wi[src]);
    g_Wh_r[idx] = __float2half_rn(Wh[src]);
    if (k == 0)
        g_bias_r[l * G4 + np] = bi[l * G4 + s * 512 + j] + bh[l * G4 + s * 512 + j];
}

// ---------------- big input-projection GEMM ---------------------------------
// C[65536, 2048] = A[65536, 512] x Wr[2048, 512]^T + bias
// A is fp32 (layer 0: x) or fp16 (layer 1: g_hs0)
__global__ __launch_bounds__(256) void k_gemm(const float* __restrict__ Af32, int layer) {
    __shared__ unsigned As[128][20];
    __shared__ unsigned Bs[64][20];

    const __half* W    = g_Wi_r + (size_t)layer * G4 * ICH;
    const float*  bias = g_bias_r + layer * G4;
    float*        C    = g_xi;

    int n0 = blockIdx.x * 64, m0 = blockIdx.y * 128;
    int tid = threadIdx.x, lane = tid & 31, warp = tid >> 5;
    int q = lane & 3, gr = lane >> 2;
    int wm = warp & 3, wn = warp >> 2;

    float acc[2][4][4];
#pragma unroll
    for (int mi = 0; mi < 2; mi++)
#pragma unroll
        for (int ni = 0; ni < 4; ni++)
#pragma unroll
            for (int e = 0; e < 4; e++) acc[mi][ni][e] = 0.f;

    for (int k0 = 0; k0 < 512; k0 += 32) {
        if (Af32) {   // fp32 A -> fp16 smem
#pragma unroll
            for (int i = 0; i < 4; i++) {
                int f4 = tid + i * 256;
                int r = f4 >> 3, c4 = f4 & 7;
                float4 v = *(const float4*)&Af32[(size_t)(m0 + r) * 512 + k0 + c4 * 4];
                __half2 h01 = __floats2half2_rn(v.x, v.y);
                __half2 h23 = __floats2half2_rn(v.z, v.w);
                As[r][c4 * 2]     = *(unsigned*)&h01;
                As[r][c4 * 2 + 1] = *(unsigned*)&h23;
            }
        } else {      // fp16 A (g_hs0) direct
#pragma unroll
            for (int i = 0; i < 2; i++) {
                int e = tid + i * 256;             // 0..511
                int r = e >> 2, seg = e & 3;       // 4 x uint4 per row-tile
                uint4 v = *(const uint4*)&g_hs0[(size_t)(m0 + r) * 512 + k0 + seg * 8];
                *(uint4*)&As[r][seg * 4] = v;
            }
        }
#pragma unroll
        for (int i = 0; i < 2; i++) {
            int e = tid + i * 256;
            int r = e >> 3, u = e & 7;
            uint2 v = *(const uint2*)(W + (size_t)(n0 + r) * 512 + k0 + u * 4);
            Bs[r][u * 2] = v.x;
            Bs[r][u * 2 + 1] = v.y;
        }
        __syncthreads();

#pragma unroll
        for (int kt = 0; kt < 2; kt++) {
            unsigned a[2][4];
#pragma unroll
            for (int mi = 0; mi < 2; mi++) {
                int r0 = wm * 32 + mi * 16 + gr;
                a[mi][0] = As[r0][kt * 8 + q];
                a[mi][1] = As[r0 + 8][kt * 8 + q];
                a[mi][2] = As[r0][kt * 8 + q + 4];
                a[mi][3] = As[r0 + 8][kt * 8 + q + 4];
            }
#pragma unroll
            for (int ni = 0; ni < 4; ni++) {
                int br = wn * 32 + ni * 8 + gr;
                unsigned b0 = Bs[br][kt * 8 + q];
                unsigned b1 = Bs[br][kt * 8 + q + 4];
#pragma unroll
                for (int mi = 0; mi < 2; mi++)
                    mma_f16(acc[mi][ni], a[mi][0], a[mi][1], a[mi][2], a[mi][3], b0, b1);
            }
        }
        __syncthreads();
    }

#pragma unroll
    for (int mi = 0; mi < 2; mi++)
#pragma unroll
        for (int ni = 0; ni < 4; ni++) {
            int row  = m0 + wm * 32 + mi * 16 + gr;
            int ncol = n0 + wn * 32 + ni * 8 + 2 * q;
            float2 bb = *(const float2*)&bias[ncol];
            float2 o;
            o.x = acc[mi][ni][0] + bb.x; o.y = acc[mi][ni][1] + bb.y;
            *(float2*)&C[(size_t)row * G4 + ncol] = o;
            o.x = acc[mi][ni][2] + bb.x; o.y = acc[mi][ni][3] + bb.y;
            *(float2*)&C[(size_t)(row + 8) * G4 + ncol] = o;
        }
}

// ---------------- persistent recurrent kernel -------------------------------
// 128 blocks x 128 threads. Block b owns gate' rows [16b,16b+16) <-> h cols [4b,4b+4).
// Sync: single monotone counter. Arrival: tid0 fence.acq_rel.gpu + red.add (after
// bar.sync, cumulativity orders the whole block's h stores). Wait: tid0 spins on
// the counter with ld.relaxed, acquire fence, bar.sync broadcast. Only the 512B
// fp16 h-slice is under the fence; hseq DRAM stores are issued after arrival.
__global__ __launch_bounds__(128, 1) void k_lstm(int layer,
                                                 const float* __restrict__ h0l,
                                                 const float* __restrict__ c0l,
                                                 float* __restrict__ ybase,
                                                 float* __restrict__ hT,
                                                 float* __restrict__ cT) {
    __shared__ uint2 sWh[16][132];   // [gate' row local][uint2 over K=512 halves]
    __shared__ float sG[64][20];     // gate accumulators [batch][local n']

    int b = blockIdx.x, tid = threadIdx.x;
    int lane = tid & 31, warp = tid >> 5;
    int q = lane & 3, gr = lane >> 2;

    // load this block's Wh slice (16 x 512 fp16) into smem
    const uint2* WhU = (const uint2*)(g_Wh_r + (size_t)layer * G4 * HCH);
#pragma unroll
    for (int i = 0; i < 16; i++) {
        int w = tid + i * 128;
        int r = w >> 7, c = w & 127;
        sWh[r][c] = WhU[(size_t)(16 * b + r) * 128 + c];
    }

    // init c (registers) and h buffer slice, then publish (arrival #1)
    float creg[2];
#pragma unroll
    for (int s = 0; s < 2; s++) {
        int idx = tid + s * 128;
        int batch = idx >> 2, jl = idx & 3, col = 4 * b + jl;
        creg[s] = c0l[batch * HCH + col];
        g_hbuf[0][batch * HCH + col] = __float2half_rn(h0l[batch * HCH + col]);
    }
    __syncthreads();
    if (tid == 0) { fence_gpu(); red_add_relaxed(&g_cnt, 1); }

    const int rb   = 16 * warp + gr;     // batch row for A fragments
    const int base = rb * 128;
    const int b0i  = tid >> 2,  j0 = tid & 3;
    const int b1i  = (tid + 128) >> 2;

    for (int t = 0; t < T_STEPS; t++) {
        // prefetch xi_t (DRAM) before the wait
        const float* xit = g_xi + (size_t)t * BATCH * G4;
        float4 xv0 = *(const float4*)&xit[b0i * G4 + 16 * b + 4 * j0];
        float4 xv1 = *(const float4*)&xit[b1i * G4 + 16 * b + 4 * j0];

        // wait: all producers published step-t h (count >= 128*(t+1))
        if (tid == 0) {
            int need = (t + 1) * NBLK;
            while (ld_relaxed(&g_cnt) < need) {}
            fence_gpu();
        }
        __syncthreads();

        const uint2* hb = (const uint2*)g_hbuf[t & 1];
        float acc[2][4];
#pragma unroll
        for (int nt = 0; nt < 2; nt++)
#pragma unroll
            for (int e = 0; e < 4; e++) acc[nt][e] = 0.f;

        // 2-deep software pipeline over 4 batches of 8 kt-iterations.
        // uint2 covers phys k = 4*wi..4*wi+3 for BOTH A and B (same K-perm).
        uint2 va[2][8], vb[2][8];
#pragma unroll
        for (int u = 0; u < 8; u++) {
            int wi = 4 * u + q;
            va[0][u] = __ldcg(&hb[base + wi]);
            vb[0][u] = __ldcg(&hb[base + 1024 + wi]);
        }
#pragma unroll
        for (int ko = 0; ko < 4; ko++) {
            int cur = ko & 1;
            if (ko < 3) {
#pragma unroll
                for (int u = 0; u < 8; u++) {
                    int wi = 32 * (ko + 1) + 4 * u + q;
                    va[cur ^ 1][u] = __ldcg(&hb[base + wi]);
                    vb[cur ^ 1][u] = __ldcg(&hb[base + 1024 + wi]);
                }
            }
#pragma unroll
            for (int u = 0; u < 8; u++) {
                int wi = 32 * ko + 4 * u + q;
#pragma unroll
                for (int nt = 0; nt < 2; nt++) {
                    uint2 wv = sWh[nt * 8 + gr][wi];
                    mma_f16(acc[nt], va[cur][u].x, vb[cur][u].x,
                            va[cur][u].y, vb[cur][u].y, wv.x, wv.y);
                }
            }
        }

        // accumulators -> smem (natural [batch][gate'] layout)
#pragma unroll
        for (int nt = 0; nt < 2; nt++) {
            int nc = nt * 8 + 2 * q;
            *(float2*)&sG[16 * warp + gr][nc]     = make_float2(acc[nt][0], acc[nt][1]);
            *(float2*)&sG[16 * warp + gr + 8][nc] = make_float2(acc[nt][2], acc[nt][3]);
        }
        __syncthreads();

        // elementwise LSTM cell; store fp16 h slice; publish (arrival)
        __half* hn = g_hbuf[(t + 1) & 1];
        float hv[2], cv[2];
#pragma unroll
        for (int s = 0; s < 2; s++) {
            int idx = tid + s * 128;
            int batch = idx >> 2, jl = idx & 3, col = 4 * b + jl;
            float4 xv = s ? xv1 : xv0;
            float f  = sigmf(sG[batch][4 * jl + 0] + xv.x);
            float ii = sigmf(sG[batch][4 * jl + 1] + xv.y);
            float o  = sigmf(sG[batch][4 * jl + 2] + xv.z);
            float g  = tanhfast(sG[batch][4 * jl + 3] + xv.w);
            float c  = creg[s] * f + ii * g;
            creg[s]  = c;
            float h  = o * tanhfast(c);
            hv[s] = h; cv[s] = c;
            hn[batch * HCH + col] = __float2half_rn(h);
        }
        __syncthreads();
        if (tid == 0) { fence_gpu(); red_add_relaxed(&g_cnt, 1); }

        // off-critical-path: sequence output (+ finals)
#pragma unroll
        for (int s = 0; s < 2; s++) {
            int idx = tid + s * 128;
            int batch = idx >> 2, jl = idx & 3, col = 4 * b + jl;
            size_t off = (size_t)t * BATCH * HCH + batch * HCH + col;
            if (layer == 0) g_hs0[off] = __float2half_rn(hv[s]);
            else            ybase[off] = hv[s];
            if (t == T_STEPS - 1) {
                hT[batch * HCH + col] = hv[s];
                cT[batch * HCH + col] = cv[s];
            }
        }
    }
}

// ---------------- launch ----------------------------------------------------
extern "C" void kernel_launch(void* const* d_in, const int* in_sizes, int n_in,
                              void* d_out, int out_size) {
    const float* x  = (const float*)d_in[0];
    const float* Wi = (const float*)d_in[1];
    const float* bi = (const float*)d_in[2];
    const float* Wh = (const float*)d_in[3];
    const float* bh = (const float*)d_in[4];
    const float* h0 = (const float*)d_in[5];
    const float* c0 = (const float*)d_in[6];

    float* out = (float*)d_out;
    float* y   = out;                                   // [T,B,HC]
    float* hsO = out + (size_t)T_STEPS * BATCH * HCH;   // [L,B,HC]
    float* csO = hsO + (size_t)NLAYER * BATCH * HCH;    // [L,B,HC]

    k_reorder<<<8192, 256>>>(Wi, bi, Wh, bh);

    // layer 0
    k_gemm<<<dim3(32, 512), 256>>>(x, 0);
    k_init<<<1, 1>>>();
    k_lstm<<<NBLK, 128>>>(0, h0, c0, y, hsO, csO);

    // layer 1
    k_gemm<<<dim3(32, 512), 256>>>(nullptr, 1);
    k_init<<<1, 1>>>();
    k_lstm<<<NBLK, 128>>>(1, h0 + BATCH * HCH, c0 + BATCH * HCH, y,
                          hsO + BATCH * HCH, csO + BATCH * HCH);

    (void)in_sizes; (void)n_in; (void)out_size;
}

// round 8
// speedup vs baseline: 2.8249x; 1.1634x over previous
#include <cuda_runtime.h>
#include <cuda_fp16.h>

#define T_STEPS 1024
#define BATCH   64
#define ICH     512
#define HCH     512
#define G4      2048
#define NLAYER  2
#define NBLK    128

// ---------------- scratch (static device globals; no allocation) ------------
__device__ __align__(16) float  g_xi[134217728];   // [T][B][2048] reused per layer
__device__ __align__(16) __half g_hs0[33554432];   // layer0 h sequence [T][B][512] fp16
__device__ __align__(16) __half g_hbuf[2][BATCH*HCH];   // PERMUTED fragment-major layout
__device__ __align__(16) __half g_Wi_r[NLAYER*G4*ICH];
__device__ __align__(16) __half g_Wh_r[NLAYER*G4*HCH];
__device__ __align__(16) float  g_bias_r[NLAYER*G4];
__device__ int g_cnt;

// Permuted h layout (uint2 granularity). Logical (batch 0..63, wd 0..127) where
// wd = col>>2. chunk=batch>>4 (consumer warp id), h_=(batch>>3)&1 (va/vb),
// gr=batch&7, inner word order (ko*8+u)*32 + lane with lane=4*gr+q, q=wd&3.
// Consumer loads become 256B lane-contiguous.
__device__ __forceinline__ int hperm_u2(int batch, int wd) {
    int inner = (((wd >> 5) * 8 + ((wd >> 2) & 7)) << 5) | ((batch & 7) << 2) | (wd & 3);
    return ((batch >> 4) << 11) | (((batch >> 3) & 1) << 10) | inner;
}

// ---------------- helpers ---------------------------------------------------
__device__ __forceinline__ void mma_f16(float acc[4],
                                        unsigned a0, unsigned a1, unsigned a2, unsigned a3,
                                        unsigned b0, unsigned b1) {
    asm volatile(
        "mma.sync.aligned.m16n8k16.row.col.f32.f16.f16.f32 "
        "{%0,%1,%2,%3},{%4,%5,%6,%7},{%8,%9},{%0,%1,%2,%3};"
        : "+f"(acc[0]), "+f"(acc[1]), "+f"(acc[2]), "+f"(acc[3])
        : "r"(a0), "r"(a1), "r"(a2), "r"(a3), "r"(b0), "r"(b1));
}

__device__ __forceinline__ float sigmf(float x) {
    return __fdividef(1.f, 1.f + __expf(-x));
}
__device__ __forceinline__ float tanhfast(float x) {
    float e = __expf(2.f * x);
    return 1.f - __fdividef(2.f, e + 1.f);
}

__device__ __forceinline__ int ld_relaxed(const int* p) {
    int v;
    asm volatile("ld.relaxed.gpu.global.b32 %0, [%1];" : "=r"(v) : "l"(p) : "memory");
    return v;
}
__device__ __forceinline__ void red_add_relaxed(int* p, int v) {
    asm volatile("red.relaxed.gpu.global.add.s32 [%0], %1;" :: "l"(p), "r"(v) : "memory");
}
__device__ __forceinline__ void fence_gpu() {
    asm volatile("fence.acq_rel.gpu;" ::: "memory");
}

// ---------------- init: reset counter (needed per graph replay) -------------
__global__ void k_init() { g_cnt = 0; }

// ---------------- reorder weights to interleaved-gate fp16 ------------------
// dest row n' = 4*j + s  <->  source row s*512 + j   (s in {f,i,o,g})
__global__ void k_reorder(const float* __restrict__ Wi, const float* __restrict__ bi,
                          const float* __restrict__ Wh, const float* __restrict__ bh) {
    unsigned idx = blockIdx.x * 256u + threadIdx.x;   // over 2*2048*512 = 2097152
    if (idx >= 2097152u) return;
    int k  = idx & 511;
    int np = (idx >> 9) & 2047;
    int l  = idx >> 20;
    int s  = np & 3;
    int j  = np >> 2;
    size_t src = ((size_t)l * G4 + s * 512 + j) * 512 + k;
    g_Wi_r[idx] = __float2half_rn(Wi[src]);
    g_Wh_r[idx] = __float2half_rn(Wh[src]);
    if (k == 0)
        g_bias_r[l * G4 + np] = bi[l * G4 + s * 512 + j] + bh[l * G4 + s * 512 + j];
}

// ---------------- big input-projection GEMM ---------------------------------
// C[65536, 2048] = A[65536, 512] x Wr[2048, 512]^T + bias
// A is fp32 (layer 0: x) or fp16 (layer 1: g_hs0)
__global__ __launch_bounds__(256) void k_gemm(const float* __restrict__ Af32, int layer) {
    __shared__ unsigned As[128][20];
    __shared__ unsigned Bs[64][20];

    const __half* W    = g_Wi_r + (size_t)layer * G4 * ICH;
    const float*  bias = g_bias_r + layer * G4;
    float*        C    = g_xi;

    int n0 = blockIdx.x * 64, m0 = blockIdx.y * 128;
    int tid = threadIdx.x, lane = tid & 31, warp = tid >> 5;
    int q = lane & 3, gr = lane >> 2;
    int wm = warp & 3, wn = warp >> 2;

    float acc[2][4][4];
#pragma unroll
    for (int mi = 0; mi < 2; mi++)
#pragma unroll
        for (int ni = 0; ni < 4; ni++)
#pragma unroll
            for (int e = 0; e < 4; e++) acc[mi][ni][e] = 0.f;

    for (int k0 = 0; k0 < 512; k0 += 32) {
        if (Af32) {   // fp32 A -> fp16 smem
#pragma unroll
            for (int i = 0; i < 4; i++) {
                int f4 = tid + i * 256;
                int r = f4 >> 3, c4 = f4 & 7;
                float4 v = *(const float4*)&Af32[(size_t)(m0 + r) * 512 + k0 + c4 * 4];
                __half2 h01 = __floats2half2_rn(v.x, v.y);
                __half2 h23 = __floats2half2_rn(v.z, v.w);
                As[r][c4 * 2]     = *(unsigned*)&h01;
                As[r][c4 * 2 + 1] = *(unsigned*)&h23;
            }
        } else {      // fp16 A (g_hs0) direct
#pragma unroll
            for (int i = 0; i < 2; i++) {
                int e = tid + i * 256;
                int r = e >> 2, seg = e & 3;
                uint4 v = *(const uint4*)&g_hs0[(size_t)(m0 + r) * 512 + k0 + seg * 8];
                *(uint4*)&As[r][seg * 4] = v;
            }
        }
#pragma unroll
        for (int i = 0; i < 2; i++) {
            int e = tid + i * 256;
            int r = e >> 3, u = e & 7;
            uint2 v = *(const uint2*)(W + (size_t)(n0 + r) * 512 + k0 + u * 4);
            Bs[r][u * 2] = v.x;
            Bs[r][u * 2 + 1] = v.y;
        }
        __syncthreads();

#pragma unroll
        for (int kt = 0; kt < 2; kt++) {
            unsigned a[2][4];
#pragma unroll
            for (int mi = 0; mi < 2; mi++) {
                int r0 = wm * 32 + mi * 16 + gr;
                a[mi][0] = As[r0][kt * 8 + q];
                a[mi][1] = As[r0 + 8][kt * 8 + q];
                a[mi][2] = As[r0][kt * 8 + q + 4];
                a[mi][3] = As[r0 + 8][kt * 8 + q + 4];
            }
#pragma unroll
            for (int ni = 0; ni < 4; ni++) {
                int br = wn * 32 + ni * 8 + gr;
                unsigned b0 = Bs[br][kt * 8 + q];
                unsigned b1 = Bs[br][kt * 8 + q + 4];
#pragma unroll
                for (int mi = 0; mi < 2; mi++)
                    mma_f16(acc[mi][ni], a[mi][0], a[mi][1], a[mi][2], a[mi][3], b0, b1);
            }
        }
        __syncthreads();
    }

#pragma unroll
    for (int mi = 0; mi < 2; mi++)
#pragma unroll
        for (int ni = 0; ni < 4; ni++) {
            int row  = m0 + wm * 32 + mi * 16 + gr;
            int ncol = n0 + wn * 32 + ni * 8 + 2 * q;
            float2 bb = *(const float2*)&bias[ncol];
            float2 o;
            o.x = acc[mi][ni][0] + bb.x; o.y = acc[mi][ni][1] + bb.y;
            *(float2*)&C[(size_t)row * G4 + ncol] = o;
            o.x = acc[mi][ni][2] + bb.x; o.y = acc[mi][ni][3] + bb.y;
            *(float2*)&C[(size_t)(row + 8) * G4 + ncol] = o;
        }
}

// ---------------- persistent recurrent kernel -------------------------------
// 128 blocks x 128 threads. Block b owns gate' rows [16b,16b+16) <-> h cols [4b,4b+4).
// h ping-pong buffers use the PERMUTED fragment-major layout so every consumer
// LDG.64 is 256B lane-contiguous (2 L1tex wavefronts instead of 8).
__global__ __launch_bounds__(128, 1) void k_lstm(int layer,
                                                 const float* __restrict__ h0l,
                                                 const float* __restrict__ c0l,
                                                 float* __restrict__ ybase,
                                                 float* __restrict__ hT,
                                                 float* __restrict__ cT) {
    __shared__ uint2 sWh[16][132];   // [gate' row local][uint2 over K=512 halves]
    __shared__ float sG[64][20];     // gate accumulators [batch][local n']

    int b = blockIdx.x, tid = threadIdx.x;
    int lane = tid & 31, warp = tid >> 5;
    int q = lane & 3, gr = lane >> 2;

    // load this block's Wh slice (16 x 512 fp16) into smem
    const uint2* WhU = (const uint2*)(g_Wh_r + (size_t)layer * G4 * HCH);
#pragma unroll
    for (int i = 0; i < 16; i++) {
        int w = tid + i * 128;
        int r = w >> 7, c = w & 127;
        sWh[r][c] = WhU[(size_t)(16 * b + r) * 128 + c];
    }

    // This block writes only uint2-word wd = b of each batch row (cols 4b..4b+3).
    const int wd_b = b;   // wd = col>>2 = b for all 4 owned cols

    // init c (registers) and h buffer slice (permuted), publish (arrival #1)
    float creg[2];
#pragma unroll
    for (int s = 0; s < 2; s++) {
        int idx = tid + s * 128;
        int batch = idx >> 2, jl = idx & 3, col = 4 * b + jl;
        creg[s] = c0l[batch * HCH + col];
        ((__half*)g_hbuf[0])[4 * hperm_u2(batch, wd_b) + jl] =
            __float2half_rn(h0l[batch * HCH + col]);
    }
    __syncthreads();
    if (tid == 0) { fence_gpu(); red_add_relaxed(&g_cnt, 1); }

    const int lbase = warp * 2048 + lane;   // uint2 base for this thread's fragments
    const int b0i  = tid >> 2,  j0 = tid & 3;
    const int b1i  = (tid + 128) >> 2;

    for (int t = 0; t < T_STEPS; t++) {
        // prefetch xi_t (DRAM) before the wait
        const float* xit = g_xi + (size_t)t * BATCH * G4;
        float4 xv0 = *(const float4*)&xit[b0i * G4 + 16 * b + 4 * j0];
        float4 xv1 = *(const float4*)&xit[b1i * G4 + 16 * b + 4 * j0];

        // wait: all producers published step-t h (count >= 128*(t+1))
        if (tid == 0) {
            int need = (t + 1) * NBLK;
            while (ld_relaxed(&g_cnt) < need) {}
            fence_gpu();
        }
        __syncthreads();

        const uint2* hb = (const uint2*)g_hbuf[t & 1];
        float acc[2][4];
#pragma unroll
        for (int nt = 0; nt < 2; nt++)
#pragma unroll
            for (int e = 0; e < 4; e++) acc[nt][e] = 0.f;

        // 2-deep software pipeline; each LDG.64 is 256B lane-contiguous.
        uint2 va[2][8], vb[2][8];
#pragma unroll
        for (int u = 0; u < 8; u++) {
            va[0][u] = __ldcg(&hb[lbase + u * 32]);
            vb[0][u] = __ldcg(&hb[lbase + 1024 + u * 32]);
        }
#pragma unroll
        for (int ko = 0; ko < 4; ko++) {
            int cur = ko & 1;
            if (ko < 3) {
#pragma unroll
                for (int u = 0; u < 8; u++) {
                    int off = (ko + 1) * 256 + u * 32;
                    va[cur ^ 1][u] = __ldcg(&hb[lbase + off]);
                    vb[cur ^ 1][u] = __ldcg(&hb[lbase + 1024 + off]);
                }
            }
#pragma unroll
            for (int u = 0; u < 8; u++) {
                int wi = 32 * ko + 4 * u + q;
#pragma unroll
                for (int nt = 0; nt < 2; nt++) {
                    uint2 wv = sWh[nt * 8 + gr][wi];
                    mma_f16(acc[nt], va[cur][u].x, vb[cur][u].x,
                            va[cur][u].y, vb[cur][u].y, wv.x, wv.y);
                }
            }
        }

        // accumulators -> smem (natural [batch][gate'] layout)
#pragma unroll
        for (int nt = 0; nt < 2; nt++) {
            int nc = nt * 8 + 2 * q;
            *(float2*)&sG[16 * warp + gr][nc]     = make_float2(acc[nt][0], acc[nt][1]);
            *(float2*)&sG[16 * warp + gr + 8][nc] = make_float2(acc[nt][2], acc[nt][3]);
        }
        __syncthreads();

        // elementwise LSTM cell; store permuted fp16 h slice; publish
        __half* hn = (__half*)g_hbuf[(t + 1) & 1];
        float hv[2], cv[2];
#pragma unroll
        for (int s = 0; s < 2; s++) {
            int idx = tid + s * 128;
            int batch = idx >> 2, jl = idx & 3;
            float4 xv = s ? xv1 : xv0;
            float f  = sigmf(sG[batch][4 * jl + 0] + xv.x);
            float ii = sigmf(sG[batch][4 * jl + 1] + xv.y);
            float o  = sigmf(sG[batch][4 * jl + 2] + xv.z);
            float g  = tanhfast(sG[batch][4 * jl + 3] + xv.w);
            float c  = creg[s] * f + ii * g;
            creg[s]  = c;
            float h  = o * tanhfast(c);
            hv[s] = h; cv[s] = c;
            hn[4 * hperm_u2(batch, wd_b) + jl] = __float2half_rn(h);
        }
        __syncthreads();
        if (tid == 0) { fence_gpu(); red_add_relaxed(&g_cnt, 1); }

        // off-critical-path: sequence output (+ finals), plain layout
#pragma unroll
        for (int s = 0; s < 2; s++) {
            int idx = tid + s * 128;
            int batch = idx >> 2, jl = idx & 3, col = 4 * b + jl;
            size_t off = (size_t)t * BATCH * HCH + batch * HCH + col;
            if (layer == 0) g_hs0[off] = __float2half_rn(hv[s]);
            else            ybase[off] = hv[s];
            if (t == T_STEPS - 1) {
                hT[batch * HCH + col] = hv[s];
                cT[batch * HCH + col] = cv[s];
            }
        }
    }
}

// ---------------- launch ----------------------------------------------------
extern "C" void kernel_launch(void* const* d_in, const int* in_sizes, int n_in,
                              void* d_out, int out_size) {
    const float* x  = (const float*)d_in[0];
    const float* Wi = (const float*)d_in[1];
    const float* bi = (const float*)d_in[2];
    const float* Wh = (const float*)d_in[3];
    const float* bh = (const float*)d_in[4];
    const float* h0 = (const float*)d_in[5];
    const float* c0 = (const float*)d_in[6];

    float* out = (float*)d_out;
    float* y   = out;                                   // [T,B,HC]
    float* hsO = out + (size_t)T_STEPS * BATCH * HCH;   // [L,B,HC]
    float* csO = hsO + (size_t)NLAYER * BATCH * HCH;    // [L,B,HC]

    k_reorder<<<8192, 256>>>(Wi, bi, Wh, bh);

    // layer 0
    k_gemm<<<dim3(32, 512), 256>>>(x, 0);
    k_init<<<1, 1>>>();
    k_lstm<<<NBLK, 128>>>(0, h0, c0, y, hsO, csO);

    // layer 1
    k_gemm<<<dim3(32, 512), 256>>>(nullptr, 1);
    k_init<<<1, 1>>>();
    k_lstm<<<NBLK, 128>>>(1, h0 + BATCH * HCH, c0 + BATCH * HCH, y,
                          hsO + BATCH * HCH, csO + BATCH * HCH);

    (void)in_sizes; (void)n_in; (void)out_size;
}

// round 10
// speedup vs baseline: 4.5251x; 1.6019x over previous
#include <cuda_runtime.h>
#include <cuda_fp16.h>

#define T_STEPS 1024
#define BATCH   64
#define ICH     512
#define HCH     512
#define G4      2048
#define NBLK    128
#define NTHR    256

// ---------------- scratch (static device globals; no allocation) ------------
__device__ __align__(16) float  g_xi[134217728];       // [T][B][2048] layer0 xi (512MB)
__device__ __align__(16) __half g_h0[4][BATCH*HCH];    // layer0 h ring (fragment-packed)
__device__ __align__(16) __half g_h1[4][BATCH*HCH];    // layer1 h ring
__device__ __align__(16) __half g_Wi_r[G4*ICH];        // layer0 Wi row-major interleaved (GEMM)
__device__ __align__(16) uint4  g_wf0[NBLK*1024];      // layer0 Wh fragment-major
__device__ __align__(16) uint4  g_wf1[NBLK*2*1024];    // layer1 {Wi,Wh} fragment-major
__device__ __align__(16) float  g_bias_r[2*G4];        // bi+bh, interleaved, both layers
__device__ int g_cnt;

// ---------------- helpers ---------------------------------------------------
__device__ __forceinline__ void mma_f16(float acc[4],
                                        unsigned a0, unsigned a1, unsigned a2, unsigned a3,
                                        unsigned b0, unsigned b1) {
    asm volatile(
        "mma.sync.aligned.m16n8k16.row.col.f32.f16.f16.f32 "
        "{%0,%1,%2,%3},{%4,%5,%6,%7},{%8,%9},{%0,%1,%2,%3};"
        : "+f"(acc[0]), "+f"(acc[1]), "+f"(acc[2]), "+f"(acc[3])
        : "r"(a0), "r"(a1), "r"(a2), "r"(a3), "r"(b0), "r"(b1));
}
__device__ __forceinline__ float sigmf(float x) {
    return __fdividef(1.f, 1.f + __expf(-x));
}
__device__ __forceinline__ float tanhfast(float x) {
    float e = __expf(2.f * x);
    return 1.f - __fdividef(2.f, e + 1.f);
}
__device__ __forceinline__ int ld_relaxed(const int* p) {
    int v;
    asm volatile("ld.relaxed.gpu.global.b32 %0, [%1];" : "=r"(v) : "l"(p) : "memory");
    return v;
}
__device__ __forceinline__ void red_add_relaxed(int* p, int v) {
    asm volatile("red.relaxed.gpu.global.add.s32 [%0], %1;" :: "l"(p), "r"(v) : "memory");
}
__device__ __forceinline__ void fence_gpu() {
    asm volatile("fence.acq_rel.gpu;" ::: "memory");
}
__device__ __forceinline__ uint4 ldcg4(const uint4* p) { return __ldcg(p); }

// ---------------- init: reset counter (per graph replay) --------------------
__global__ void k_init() { g_cnt = 0; }

// ---------------- layer0 Wi -> row-major interleaved fp16 (for GEMM) --------
__global__ void k_reorder(const float* __restrict__ Wi) {
    unsigned idx = blockIdx.x * 256u + threadIdx.x;   // over 2048*512
    if (idx >= 1048576u) return;
    int k  = idx & 511;
    int np = idx >> 9;
    int s  = np & 3;
    int j  = np >> 2;
    g_Wi_r[idx] = __float2half_rn(Wi[(size_t)(s * 512 + j) * 512 + k]);
}

// ---------------- bias (bi+bh), interleaved, both layers --------------------
__global__ void k_bias(const float* __restrict__ bi, const float* __restrict__ bh) {
    int idx = blockIdx.x * 1024 + threadIdx.x;   // over 2*2048
    int l = idx >> 11, np = idx & 2047;
    int s = np & 3, j = np >> 2;
    g_bias_r[idx] = bi[l * G4 + s * 512 + j] + bh[l * G4 + s * 512 + j];
}

// ---------------- weight fragment tables ------------------------------------
// Fragment uint (2 halves): group G, m 0..31, lane (gr=lane>>2, q=lane&3),
// uw: nt = uw>>1, jp = uw&1.  Interleaved gate row = 16G + nt*8 + gr
// (raw row s*512+j with s=row&3, j=row>>2), k = 16m + 4q + 2jp + {0,1}.
__global__ void k_wfrag(const float* __restrict__ Wi, const float* __restrict__ Wh) {
    unsigned idx = blockIdx.x * 256u + threadIdx.x;   // over 524288 + 1048576
    if (idx >= 1572864u) return;
    unsigned fi, G, m, lane, uw;
    const float* src;
    unsigned* dst;
    if (idx < 524288u) {          // layer0 Wh fragments
        fi = idx; dst = (unsigned*)g_wf0;
        G = fi >> 12; m = (fi >> 7) & 31; lane = (fi >> 2) & 31; uw = fi & 3;
        src = Wh;                                   // layer 0 Wh
    } else {                      // layer1 {Wi,Wh}
        fi = idx - 524288u; dst = (unsigned*)g_wf1;
        G = fi >> 13;
        unsigned kc = (fi >> 12) & 1;
        m = (fi >> 7) & 31; lane = (fi >> 2) & 31; uw = fi & 3;
        src = (kc == 0) ? (Wi + (size_t)G4 * ICH) : (Wh + (size_t)G4 * HCH);
    }
    int nt = uw >> 1, jp = uw & 1;
    int gr = lane >> 2, q = lane & 3;
    int rowp = 16 * G + nt * 8 + gr;
    int s = rowp & 3, jr = rowp >> 2;
    int k = 16 * m + 4 * q + 2 * jp;
    const float* p = src + (size_t)(s * 512 + jr) * 512 + k;
    __half2 h = __floats2half2_rn(p[0], p[1]);
    dst[fi] = *(unsigned*)&h;
}

// ---------------- layer0 input-projection GEMM ------------------------------
// C[65536, 2048] = x[65536, 512] (fp32->fp16) x Wi0r[2048, 512]^T + bias0
__global__ __launch_bounds__(256) void k_gemm(const float* __restrict__ A) {
    __shared__ unsigned As[128][20];
    __shared__ unsigned Bs[64][20];

    const __half* W    = g_Wi_r;
    const float*  bias = g_bias_r;
    float*        C    = g_xi;

    int n0 = blockIdx.x * 64, m0 = blockIdx.y * 128;
    int tid = threadIdx.x, lane = tid & 31, warp = tid >> 5;
    int q = lane & 3, gr = lane >> 2;
    int wm = warp & 3, wn = warp >> 2;

    float acc[2][4][4];
#pragma unroll
    for (int mi = 0; mi < 2; mi++)
#pragma unroll
        for (int ni = 0; ni < 4; ni++)
#pragma unroll
            for (int e = 0; e < 4; e++) acc[mi][ni][e] = 0.f;

    for (int k0 = 0; k0 < 512; k0 += 32) {
#pragma unroll
        for (int i = 0; i < 4; i++) {
            int f4 = tid + i * 256;
            int r = f4 >> 3, c4 = f4 & 7;
            float4 v = *(const float4*)&A[(size_t)(m0 + r) * 512 + k0 + c4 * 4];
            __half2 h01 = __floats2half2_rn(v.x, v.y);
            __half2 h23 = __floats2half2_rn(v.z, v.w);
            As[r][c4 * 2]     = *(unsigned*)&h01;
            As[r][c4 * 2 + 1] = *(unsigned*)&h23;
        }
#pragma unroll
        for (int i = 0; i < 2; i++) {
            int e = tid + i * 256;
            int r = e >> 3, u = e & 7;
            uint2 v = *(const uint2*)(W + (size_t)(n0 + r) * 512 + k0 + u * 4);
            Bs[r][u * 2] = v.x;
            Bs[r][u * 2 + 1] = v.y;
        }
        __syncthreads();

#pragma unroll
        for (int kt = 0; kt < 2; kt++) {
            unsigned a[2][4];
#pragma unroll
            for (int mi = 0; mi < 2; mi++) {
                int r0 = wm * 32 + mi * 16 + gr;
                a[mi][0] = As[r0][kt * 8 + q];
                a[mi][1] = As[r0 + 8][kt * 8 + q];
                a[mi][2] = As[r0][kt * 8 + q + 4];
                a[mi][3] = As[r0 + 8][kt * 8 + q + 4];
            }
#pragma unroll
            for (int ni = 0; ni < 4; ni++) {
                int br = wn * 32 + ni * 8 + gr;
                unsigned b0 = Bs[br][kt * 8 + q];
                unsigned b1 = Bs[br][kt * 8 + q + 4];
#pragma unroll
                for (int mi = 0; mi < 2; mi++)
                    mma_f16(acc[mi][ni], a[mi][0], a[mi][1], a[mi][2], a[mi][3], b0, b1);
            }
        }
        __syncthreads();
    }

#pragma unroll
    for (int mi = 0; mi < 2; mi++)
#pragma unroll
        for (int ni = 0; ni < 4; ni++) {
            int row  = m0 + wm * 32 + mi * 16 + gr;
            int ncol = n0 + wn * 32 + ni * 8 + 2 * q;
            float2 bb = *(const float2*)&bias[ncol];
            float2 o;
            o.x = acc[mi][ni][0] + bb.x; o.y = acc[mi][ni][1] + bb.y;
            *(float2*)&C[(size_t)row * G4 + ncol] = o;
            o.x = acc[mi][ni][2] + bb.x; o.y = acc[mi][ni][3] + bb.y;
            *(float2*)&C[(size_t)(row + 8) * G4 + ncol] = o;
        }
}

// ---------------- fused 2-layer persistent recurrent kernel -----------------
// 128 blocks x 256 threads. Block b owns, for BOTH layers, gate' rows
// [16b,16b+16) <-> h cols [4b,4b+4).  Round r: layer0 step r (K=512) and
// layer1 step r-2 (K=1024: Wi1*h0 + Wh1*h1).  K is split across warp-halves
// (partial sums in smem, summed in the cell).  4-deep h rings license the lag.
__global__ __launch_bounds__(NTHR, 1) void k_fused(const float* __restrict__ h0in,
                                                   const float* __restrict__ c0in,
                                                   float* __restrict__ y,
                                                   float* __restrict__ hT,
                                                   float* __restrict__ cT) {
    __shared__ float sGp[4][64][20];   // partial gates: [0,1]=L0 halves, [2,3]=L1

    int b = blockIdx.x, tid = threadIdx.x;
    int lane = tid & 31, w = tid >> 5;
    int q = lane & 3, gr = lane >> 2;
    int chunk = w & 3, half = w >> 2;

    int batch = tid >> 2, jl = tid & 3;
    int col = 4 * b + jl;

    // publish address (half granularity) in the fragment-packed h rings
    int u4i = (batch >> 4) * 1024 + (b >> 2) * 32 + ((batch & 7) << 2) + (b & 3);
    int haddr = u4i * 8 + ((batch >> 3) & 1) * 4 + jl;

    // init c and h_0 for both layers, publish (arrival #1)
    float creg0 = c0in[batch * HCH + col];
    float creg1 = c0in[BATCH * HCH + batch * HCH + col];
    ((__half*)g_h0[0])[haddr] = __float2half_rn(h0in[batch * HCH + col]);
    ((__half*)g_h1[0])[haddr] = __float2half_rn(h0in[BATCH * HCH + batch * HCH + col]);
    __syncthreads();
    if (tid == 0) { fence_gpu(); red_add_relaxed(&g_cnt, 1); }

    float4 bb = *(const float4*)&g_bias_r[G4 + 16 * b + 4 * jl];   // layer1 bias

    const uint4* wA = g_wf0 + b * 1024;                 // + m*32 + lane
    const uint4* wB = g_wf1 + (b * 2 + half) * 1024;
    const int mA0  = 16 * half;                         // phase-A m range
    const int loff = chunk * 1024 + lane;

    for (int r = 0; r < 1026; ++r) {
        // prefetch xi_r before the wait
        float4 xv = make_float4(0.f, 0.f, 0.f, 0.f);
        if (r < T_STEPS)
            xv = __ldcg((const float4*)&g_xi[(size_t)r * BATCH * G4 + batch * G4 + 16 * b + 4 * jl]);

        // wait: all round r-1 publications visible
        if (tid == 0) {
            int need = (r + 1) * NBLK;
            while (ld_relaxed(&g_cnt) < need) {}
            fence_gpu();
        }
        __syncthreads();

        // ---- phase A: layer0 step r (K=512 split: this warp does 16 m) ----
        if (r < T_STEPS) {
            const uint4* hA = (const uint4*)g_h0[r & 3] + loff;
            float acc[2][4] = {{0.f,0.f,0.f,0.f},{0.f,0.f,0.f,0.f}};
            uint4 hr[3][4], wr[3][4];
#pragma unroll
            for (int st = 0; st < 2; st++)
#pragma unroll
                for (int u = 0; u < 4; u++) {
                    int m = mA0 + 4 * st + u;
                    hr[st][u] = ldcg4(hA + m * 32);
                    wr[st][u] = __ldg(wA + m * 32 + lane);
                }
#pragma unroll
            for (int st = 0; st < 4; st++) {
                if (st + 2 < 4) {
                    int bn = (st + 2) % 3;
#pragma unroll
                    for (int u = 0; u < 4; u++) {
                        int m = mA0 + 4 * (st + 2) + u;
                        hr[bn][u] = ldcg4(hA + m * 32);
                        wr[bn][u] = __ldg(wA + m * 32 + lane);
                    }
                }
                int c = st % 3;
#pragma unroll
                for (int u = 0; u < 4; u++) {
                    mma_f16(acc[0], hr[c][u].x, hr[c][u].z, hr[c][u].y, hr[c][u].w,
                            wr[c][u].x, wr[c][u].y);
                    mma_f16(acc[1], hr[c][u].x, hr[c][u].z, hr[c][u].y, hr[c][u].w,
                            wr[c][u].z, wr[c][u].w);
                }
            }
#pragma unroll
            for (int nt = 0; nt < 2; nt++) {
                *(float2*)&sGp[half][16 * chunk + gr][nt * 8 + 2 * q] =
                    make_float2(acc[nt][0], acc[nt][1]);
                *(float2*)&sGp[half][16 * chunk + gr + 8][nt * 8 + 2 * q] =
                    make_float2(acc[nt][2], acc[nt][3]);
            }
        }

        // ---- phase B: layer1 step r-2 (this warp: 32 m of Wi1 or Wh1) ----
        if (r >= 2) {
            const uint4* hB = (half == 0)
                ? (const uint4*)g_h0[(r - 1) & 3] + loff     // x-input = h0_{r-2} output
                : (const uint4*)g_h1[(r - 2) & 3] + loff;    // recurrent h1_{r-3} output
            float acc[2][4] = {{0.f,0.f,0.f,0.f},{0.f,0.f,0.f,0.f}};
            uint4 hr[3][4], wr[3][4];
#pragma unroll
            for (int st = 0; st < 2; st++)
#pragma unroll
                for (int u = 0; u < 4; u++) {
                    int m = 4 * st + u;
                    hr[st][u] = ldcg4(hB + m * 32);
                    wr[st][u] = __ldg(wB + m * 32 + lane);
                }
#pragma unroll
            for (int st = 0; st < 8; st++) {
                if (st + 2 < 8) {
                    int bn = (st + 2) % 3;
#pragma unroll
                    for (int u = 0; u < 4; u++) {
                        int m = 4 * (st + 2) + u;
                        hr[bn][u] = ldcg4(hB + m * 32);
                        wr[bn][u] = __ldg(wB + m * 32 + lane);
                    }
                }
                int c = st % 3;
#pragma unroll
                for (int u = 0; u < 4; u++) {
                    mma_f16(acc[0], hr[c][u].x, hr[c][u].z, hr[c][u].y, hr[c][u].w,
                            wr[c][u].x, wr[c][u].y);
                    mma_f16(acc[1], hr[c][u].x, hr[c][u].z, hr[c][u].y, hr[c][u].w,
                            wr[c][u].z, wr[c][u].w);
                }
            }
#pragma unroll
            for (int nt = 0; nt < 2; nt++) {
                *(float2*)&sGp[2 + half][16 * chunk + gr][nt * 8 + 2 * q] =
                    make_float2(acc[nt][0], acc[nt][1]);
                *(float2*)&sGp[2 + half][16 * chunk + gr + 8][nt * 8 + 2 * q] =
                    make_float2(acc[nt][2], acc[nt][3]);
            }
        }
        __syncthreads();

        // ---- cells: sum K-split partials, update, publish ----
        float hv0 = 0.f, hv1 = 0.f;
        if (r < T_STEPS) {
            float s0 = sGp[0][batch][4 * jl + 0] + sGp[1][batch][4 * jl + 0] + xv.x;
            float s1 = sGp[0][batch][4 * jl + 1] + sGp[1][batch][4 * jl + 1] + xv.y;
            float s2 = sGp[0][batch][4 * jl + 2] + sGp[1][batch][4 * jl + 2] + xv.z;
            float s3 = sGp[0][batch][4 * jl + 3] + sGp[1][batch][4 * jl + 3] + xv.w;
            float f  = sigmf(s0), ii = sigmf(s1), o = sigmf(s2), g = tanhfast(s3);
            float c  = creg0 * f + ii * g;
            creg0 = c;
            hv0 = o * tanhfast(c);
            ((__half*)g_h0[(r + 1) & 3])[haddr] = __float2half_rn(hv0);
        }
        if (r >= 2) {
            float s0 = sGp[2][batch][4 * jl + 0] + sGp[3][batch][4 * jl + 0] + bb.x;
            float s1 = sGp[2][batch][4 * jl + 1] + sGp[3][batch][4 * jl + 1] + bb.y;
            float s2 = sGp[2][batch][4 * jl + 2] + sGp[3][batch][4 * jl + 2] + bb.z;
            float s3 = sGp[2][batch][4 * jl + 3] + sGp[3][batch][4 * jl + 3] + bb.w;
            float f  = sigmf(s0), ii = sigmf(s1), o = sigmf(s2), g = tanhfast(s3);
            float c  = creg1 * f + ii * g;
            creg1 = c;
            hv1 = o * tanhfast(c);
            ((__half*)g_h1[(r - 1) & 3])[haddr] = __float2half_rn(hv1);
        }
        __syncthreads();
        if (tid == 0 && r < 1025) { fence_gpu(); red_add_relaxed(&g_cnt, 1); }

        // ---- off-critical-path outputs ----
        if (r >= 2) {
            y[(size_t)(r - 2) * BATCH * HCH + batch * HCH + col] = hv1;
            if (r == 1025) {
                hT[BATCH * HCH + batch * HCH + col] = hv1;
                cT[BATCH * HCH + batch * HCH + col] = creg1;
            }
        }
        if (r == T_STEPS - 1) {
            hT[batch * HCH + col] = hv0;
            cT[batch * HCH + col] = creg0;
        }
    }
}

// ---------------- launch ----------------------------------------------------
extern "C" void kernel_launch(void* const* d_in, const int* in_sizes, int n_in,
                              void* d_out, int out_size) {
    const float* x  = (const float*)d_in[0];
    const float* Wi = (const float*)d_in[1];
    const float* bi = (const float*)d_in[2];
    const float* Wh = (const float*)d_in[3];
    const float* bh = (const float*)d_in[4];
    const float* h0 = (const float*)d_in[5];
    const float* c0 = (const float*)d_in[6];

    float* out = (float*)d_out;
    float* y   = out;                                   // [T,B,HC]
    float* hsO = out + (size_t)T_STEPS * BATCH * HCH;   // [L,B,HC]
    float* csO = hsO + (size_t)2 * BATCH * HCH;         // [L,B,HC]

    k_reorder<<<4096, 256>>>(Wi);
    k_bias<<<4, 1024>>>(bi, bh);
    k_wfrag<<<6144, 256>>>(Wi, Wh);
    k_gemm<<<dim3(32, 512), 256>>>(x);
    k_init<<<1, 1>>>();
    k_fused<<<NBLK, NTHR>>>(h0, c0, y, hsO, csO);

    (void)in_sizes; (void)n_in; (void)out_size;
}